// round 17
// baseline (speedup 1.0000x reference)
#include <cuda_runtime.h>
#include <cuda_bf16.h>
#include <float.h>

// Segmented exact 3-NN cosine-consistency loss, SINGLE persistent kernel.
// 512 blocks x 256 threads, all co-resident (launch_bounds(256,4): <=64
// regs, ~2KB smem -> >=4 blocks/SM on 148 SMs = 592 slots >= 512), so
// grid-wide sense-reversing spin barriers are deadlock-free.
// Phases: bbox | count | scan(blk0) | scatter | knn+loss (4 lanes/point,
// lexicographic (d2,j) compare == jax.lax.top_k lower-index tie-break,
// scatter-order independent) | per-block partials + state reset | final sum.
// All reductions fixed-shape -> deterministic. No early returns: every
// thread reaches every barrier.

#define G       8
#define NC      (G * G * G)
#define MAXPTS  32768
#define MAXCELL 16384
#define TB      256
#define NBLK    512
#define LPP     4

__device__ unsigned g_bbox[6] = {0xFFFFFFFFu, 0xFFFFFFFFu, 0xFFFFFFFFu, 0u, 0u, 0u};
__device__ unsigned g_barCnt   = 0;
__device__ unsigned g_barSense = 0;
__device__ int      g_binCnt[MAXCELL];          // zero-initialized
__device__ int      g_binOff[MAXCELL];
__device__ int      g_binFill[MAXCELL];
__device__ int      g_cellOf[MAXPTS];
__device__ int      g_sortedIdx[MAXPTS];
__device__ int      g_cellSorted[MAXPTS];
__device__ float4   g_packed[MAXPTS];           // binned: (-2x,-2y,-2z,|c|^2)
__device__ float    g_loss[MAXPTS];             // by original id
__device__ float    g_partials[NBLK];

__device__ __forceinline__ void grid_barrier() {
    __syncthreads();
    if (threadIdx.x == 0) {
        const unsigned gen = *((volatile unsigned*)&g_barSense);
        __threadfence();
        if (atomicAdd(&g_barCnt, 1) == NBLK - 1) {
            g_barCnt = 0;
            __threadfence();
            atomicAdd(&g_barSense, 1);
        } else {
            while (*((volatile unsigned*)&g_barSense) == gen) { __nanosleep(32); }
        }
    }
    __syncthreads();
    __threadfence();
}

__device__ __forceinline__ unsigned encf(float f) {
    unsigned u = __float_as_uint(f);
    return (u & 0x80000000u) ? ~u : (u | 0x80000000u);
}
__device__ __forceinline__ float decf(unsigned u) {
    u = (u & 0x80000000u) ? (u ^ 0x80000000u) : ~u;
    return __uint_as_float(u);
}
__device__ __forceinline__ float dot3(float ax, float ay, float az,
                                      float bx, float by, float bz) {
    return fmaf(ax, bx, fmaf(ay, by, az * bz));
}
__device__ __forceinline__ bool lessDJ(float da, int ja, float db, int jb) {
    return (da < db) || (da == db && ja < jb);
}
__device__ __forceinline__ void insDJ(float d, int j,
                                      float& D0, int& J0,
                                      float& D1, int& J1,
                                      float& D2, int& J2) {
    if (lessDJ(d, j, D2, J2)) {
        if (lessDJ(d, j, D1, J1)) {
            D2 = D1; J2 = J1;
            if (lessDJ(d, j, D0, J0)) { D1 = D0; J1 = J0; D0 = d; J0 = j; }
            else                      { D1 = d;  J1 = j; }
        } else { D2 = d; J2 = j; }
    }
}
__device__ __forceinline__ void loadGridParams(float* lo, float* cw, float* sc) {
    #pragma unroll
    for (int a = 0; a < 3; a++) {
        const float l = decf(g_bbox[a]);
        const float h = decf(g_bbox[3 + a]);
        const float span = fmaxf(h - l, 1e-20f);
        lo[a] = l;
        cw[a] = span / (float)G;
        sc[a] = (float)G * (1.0f - 1e-6f) / span;
    }
}
__device__ __forceinline__ int cellIdx(float v, float lo, float sc) {
    int c = (int)((v - lo) * sc);
    return min(G - 1, max(0, c));
}

__global__ void __launch_bounds__(TB, 4)
fused_kernel(const float* __restrict__ pred,
             const float* __restrict__ coord,
             const float* __restrict__ target,
             float* __restrict__ out,
             int npts, int seg, int ncells, float invCount) {
    const int tid  = threadIdx.x;
    const int gtid = blockIdx.x * TB + tid;
    __shared__ unsigned shu[TB];
    __shared__ float    shf[TB];
    __shared__ int      shi[TB / 32 * 2];

    // ---------- phase 1: bbox ----------
    {
        unsigned mn[3] = {0xFFFFFFFFu, 0xFFFFFFFFu, 0xFFFFFFFFu};
        unsigned mx[3] = {0u, 0u, 0u};
        for (int i = gtid; i < npts; i += NBLK * TB) {
            #pragma unroll
            for (int a = 0; a < 3; a++) {
                const unsigned e = encf(coord[3 * i + a]);
                mn[a] = min(mn[a], e);
                mx[a] = max(mx[a], e);
            }
        }
        #pragma unroll
        for (int a = 0; a < 3; a++) {
            shu[tid] = mn[a]; __syncthreads();
            for (int s = TB / 2; s > 0; s >>= 1) {
                if (tid < s) shu[tid] = min(shu[tid], shu[tid + s]);
                __syncthreads();
            }
            if (tid == 0) atomicMin(&g_bbox[a], shu[0]);
            __syncthreads();
            shu[tid] = mx[a]; __syncthreads();
            for (int s = TB / 2; s > 0; s >>= 1) {
                if (tid < s) shu[tid] = max(shu[tid], shu[tid + s]);
                __syncthreads();
            }
            if (tid == 0) atomicMax(&g_bbox[3 + a], shu[0]);
            __syncthreads();
        }
    }
    grid_barrier();

    // ---------- phase 2: count ----------
    float lo[3], cw[3], sc[3];
    loadGridParams(lo, cw, sc);
    if (gtid < npts) {
        const int i = gtid;
        const int cx = cellIdx(coord[3 * i + 0], lo[0], sc[0]);
        const int cy = cellIdx(coord[3 * i + 1], lo[1], sc[1]);
        const int cz = cellIdx(coord[3 * i + 2], lo[2], sc[2]);
        const int cell = (i / seg) * NC + (cz * G + cy) * G + cx;
        g_cellOf[i] = cell;
        atomicAdd(&g_binCnt[cell], 1);
    }
    grid_barrier();

    // ---------- phase 3: scan (block 0 only) ----------
    if (blockIdx.x == 0) {
        const int per  = (ncells + TB - 1) / TB;
        const int lane = tid & 31;
        const int wrp  = tid >> 5;
        int tot = 0;
        for (int q = 0; q < per; q++) {
            const int idx = tid * per + q;
            if (idx < ncells) tot += g_binCnt[idx];
        }
        int inc = tot;
        #pragma unroll
        for (int off = 1; off < 32; off <<= 1) {
            const int v = __shfl_up_sync(0xffffffffu, inc, off);
            if (lane >= off) inc += v;
        }
        int* wsum = shi;
        int* wpre = shi + TB / 32;
        if (lane == 31) wsum[wrp] = inc;
        __syncthreads();
        if (tid == 0) {
            int s = 0;
            #pragma unroll
            for (int w = 0; w < TB / 32; w++) { wpre[w] = s; s += wsum[w]; }
        }
        __syncthreads();
        int o = wpre[wrp] + (inc - tot);
        for (int q = 0; q < per; q++) {
            const int idx = tid * per + q;
            if (idx < ncells) {
                g_binOff[idx]  = o;
                g_binFill[idx] = o;
                o += g_binCnt[idx];
            }
        }
    }
    grid_barrier();

    // ---------- phase 4: scatter ----------
    if (gtid < npts) {
        const int i    = gtid;
        const int cell = g_cellOf[i];
        const int pos  = atomicAdd(&g_binFill[cell], 1);
        const float x = coord[3 * i + 0];
        const float y = coord[3 * i + 1];
        const float z = coord[3 * i + 2];
        g_sortedIdx[pos]  = i;
        g_cellSorted[pos] = cell;
        g_packed[pos] = make_float4(-2.f * x, -2.f * y, -2.f * z,
                                    x * x + y * y + z * z);
    }
    grid_barrier();

    // ---------- phase 5: knn + per-point loss (4 lanes per point) ----------
    {
        const int k = gtid / LPP;               // binned position
        const int q = gtid & (LPP - 1);
        if (k < npts) {
            const int      lane = tid & 31;
            const unsigned gm   = 0xFu << (lane & ~(LPP - 1));

            const int cell     = g_cellSorted[k];
            const int i        = g_sortedIdx[k];
            const int cellBase = (cell / NC) * NC;
            const int cl       = cell - cellBase;
            const int cx       = cl & (G - 1);
            const int cy       = (cl >> 3) & (G - 1);
            const int cz       = cl >> 6;

            const float4 pk = g_packed[k];
            const float px = -0.5f * pk.x;
            const float py = -0.5f * pk.y;
            const float pz = -0.5f * pk.z;
            const float sqi = pk.w;

            float D0 = FLT_MAX, D1 = FLT_MAX, D2 = FLT_MAX;
            int   J0 = -1, J1 = -1, J2 = -1;

            for (int R = 1; R <= G; R++) {
                const int zlo = max(cz - R, 0), zhi = min(cz + R, G - 1);
                const int ylo = max(cy - R, 0), yhi = min(cy + R, G - 1);
                const int xlo = max(cx - R, 0), xhi = min(cx + R, G - 1);
                for (int zc = zlo; zc <= zhi; zc++) {
                    const int adz = abs(zc - cz);
                    for (int yc = ylo; yc <= yhi; yc++) {
                        const int ady = abs(yc - cy);
                        int sBeg[2], sEnd[2], ns = 0;
                        if (R == 1 || adz == R || ady == R) {
                            sBeg[0] = xlo; sEnd[0] = xhi; ns = 1;
                        } else {
                            if (cx - R >= 0)     { sBeg[ns] = cx - R; sEnd[ns] = cx - R; ns++; }
                            if (cx + R <= G - 1) { sBeg[ns] = cx + R; sEnd[ns] = cx + R; ns++; }
                        }
                        const int rowBase = cellBase + (zc * G + yc) * G;
                        for (int sI = 0; sI < ns; sI++) {
                            const int off = g_binOff[rowBase + sBeg[sI]];
                            const int end = g_binOff[rowBase + sEnd[sI]]
                                          + g_binCnt[rowBase + sEnd[sI]];
                            for (int t = off + q; t < end; t += LPP) {
                                const float4 c = g_packed[t];
                                const float e = fmaf(c.x, px, fmaf(c.y, py, fmaf(c.z, pz, c.w)));
                                const float d2 = fmaxf(sqi + e, 0.0f);
                                if (d2 <= D2) {
                                    const int j = g_sortedIdx[t];
                                    if (j != i) insDJ(d2, j, D0, J0, D1, J1, D2, J2);
                                }
                            }
                        }
                    }
                }

                #pragma unroll
                for (int off = 1; off < LPP; off <<= 1) {
                    const float b0 = __shfl_xor_sync(gm, D0, off);
                    const int   m0 = __shfl_xor_sync(gm, J0, off);
                    const float b1 = __shfl_xor_sync(gm, D1, off);
                    const int   m1 = __shfl_xor_sync(gm, J1, off);
                    const float b2 = __shfl_xor_sync(gm, D2, off);
                    const int   m2 = __shfl_xor_sync(gm, J2, off);
                    insDJ(b0, m0, D0, J0, D1, J1, D2, J2);
                    insDJ(b1, m1, D0, J0, D1, J1, D2, J2);
                    insDJ(b2, m2, D0, J0, D1, J1, D2, J2);
                }

                if (J2 >= 0) {
                    float b = FLT_MAX;
                    if (cx - R > 0)     b = fminf(b, px - (lo[0] + (float)(cx - R) * cw[0]));
                    if (cx + R < G - 1) b = fminf(b, (lo[0] + (float)(cx + R + 1) * cw[0]) - px);
                    if (cy - R > 0)     b = fminf(b, py - (lo[1] + (float)(cy - R) * cw[1]));
                    if (cy + R < G - 1) b = fminf(b, (lo[1] + (float)(cy + R + 1) * cw[1]) - py);
                    if (cz - R > 0)     b = fminf(b, pz - (lo[2] + (float)(cz - R) * cw[2]));
                    if (cz + R < G - 1) b = fminf(b, (lo[2] + (float)(cz + R + 1) * cw[2]) - pz);
                    if (b == FLT_MAX || D2 <= b * b) break;
                }
            }

            float acc = 0.0f;
            if (q < 3) {
                float fx = pred[3 * i + 0], fy = pred[3 * i + 1], fz = pred[3 * i + 2];
                float inpv = sqrtf(fx * fx + fy * fy + fz * fz + 1e-8f) + 1e-10f;
                float pnx = fx / inpv, pny = fy / inpv, pnz = fz / inpv;

                float tx = target[3 * i + 0], ty = target[3 * i + 1], tz = target[3 * i + 2];

                const int gj = (q == 0) ? J0 : (q == 1) ? J1 : J2;
                float qx = pred[3 * gj + 0], qy = pred[3 * gj + 1], qz = pred[3 * gj + 2];
                float inq = sqrtf(qx * qx + qy * qy + qz * qz + 1e-8f) + 1e-10f;
                float sim = fminf(fabsf(dot3(qx / inq, qy / inq, qz / inq,
                                             pnx, pny, pnz)), 1.0f);

                float ux = target[3 * gj + 0], uy = target[3 * gj + 1], uz = target[3 * gj + 2];
                float tsim = fminf(fabsf(dot3(ux, uy, uz, tx, ty, tz)), 1.0f);

                const float diff = sim - tsim;
                acc = diff * diff;
            }
            #pragma unroll
            for (int off = 1; off < LPP; off <<= 1)
                acc += __shfl_xor_sync(gm, acc, off);
            if (q == 0) g_loss[i] = acc;
        }
    }
    grid_barrier();

    // ---------- phase 6: per-block fixed-slice partials + state reset ----------
    {
        const int per = (npts + NBLK - 1) / NBLK;    // 64
        float v = 0.0f;
        if (tid < per) {
            const int idx = blockIdx.x * per + tid;
            if (idx < npts) v = g_loss[idx];
        }
        shf[tid] = v;
        __syncthreads();
        #pragma unroll
        for (int s = TB / 2; s > 0; s >>= 1) {
            if (tid < s) shf[tid] += shf[tid + s];
            __syncthreads();
        }
        if (tid == 0) g_partials[blockIdx.x] = shf[0];

        // reset state for next replay (blocks != 0 handle it)
        if (blockIdx.x != 0) {
            for (int c = (blockIdx.x - 1) * TB + tid; c < ncells;
                 c += (NBLK - 1) * TB) g_binCnt[c] = 0;
        }
        if (blockIdx.x == 1 && tid < 3) {
            g_bbox[tid] = 0xFFFFFFFFu;
            g_bbox[3 + tid] = 0u;
        }
    }
    grid_barrier();

    // ---------- phase 7: final fixed-order sum (block 0) ----------
    if (blockIdx.x == 0) {
        float v = 0.0f;
        for (int b = tid; b < NBLK; b += TB) v += g_partials[b];
        shf[tid] = v;
        __syncthreads();
        #pragma unroll
        for (int s = TB / 2; s > 0; s >>= 1) {
            if (tid < s) shf[tid] += shf[tid + s];
            __syncthreads();
        }
        if (tid == 0) out[0] = shf[0] * invCount;
    }
}

extern "C" void kernel_launch(void* const* d_in, const int* in_sizes, int n_in,
                              void* d_out, int out_size) {
    const float* pred   = (const float*)d_in[0];
    const float* coord  = (const float*)d_in[1];
    const float* target = (const float*)d_in[2];
    const int    nseg   = in_sizes[3];
    const int    npts   = in_sizes[0] / 3;
    const int    seg    = npts / nseg;
    const int    ncells = nseg * NC;

    const float invCount = 1.0f / ((float)npts * 3.0f);
    fused_kernel<<<NBLK, TB>>>(pred, coord, target, (float*)d_out,
                               npts, seg, ncells, invCount);
}